// round 13
// baseline (speedup 1.0000x reference)
#include <cuda_runtime.h>
#include <cuda_fp16.h>

#define NN 50000
#define NE 800000
#define CC 64

// ---------------- device scratch (no allocations allowed) ----------------
__device__ unsigned long long g_packed[NN]; // [cnt:24][deg fixed-point 2^-32:40]
__device__ int    g_slot[NE];               // arrival order of edge within its row
__device__ float  g_dis[NN];                // rsqrt(deg) or 0
__device__ int    g_rowstart[NN + 1];
__device__ float2 g_ecsr[NE];               // {col (bit-cast int), w} sorted by row
__device__ __half g_xh[NN * CC];            // fp16 copy of x (gather source)
__device__ __half g_T1h[NN * CC];           // T1 = L_hat @ x   (fp16)
__device__ __half g_P2h[NN * CC];           // P2 = L_hat @ T1  (fp16)

// Packed fp32x2 FMA (sm_103a FFMA2 — only reachable via PTX)
#define FMA2(d, a, b) \
    asm("fma.rn.f32x2 %0, %1, %2, %0;" : "+l"(d) : "l"(a), "l"(b))
#define PACK2(d, lo, hi) \
    asm("mov.b64 %0, {%1, %2};" : "=l"(d) : "f"(lo), "f"(hi))
#define UNPACK2(lo, hi, s) \
    asm("mov.b64 {%0, %1}, %2;" : "=f"(lo), "=f"(hi) : "l"(s))

// ---------------------------------------------------------------------------
// L1: zero g_packed, set sentinel, convert x -> fp16
// ---------------------------------------------------------------------------
__global__ void zero_convert_kernel(const float4* __restrict__ x) {
    int i = blockIdx.x * blockDim.x + threadIdx.x;
    int stride = gridDim.x * blockDim.x;
    for (int j = i; j < NN; j += stride) g_packed[j] = 0ULL;
    const int chunks = NN * CC / 8;   // 400000
    uint4* dst = (uint4*)g_xh;
    for (int c = i; c < chunks; c += stride) {
        float4 a = __ldg(&x[c * 2 + 0]);
        float4 b = __ldg(&x[c * 2 + 1]);
        half2 h0 = __floats2half2_rn(a.x, a.y);
        half2 h1 = __floats2half2_rn(a.z, a.w);
        half2 h2 = __floats2half2_rn(b.x, b.y);
        half2 h3 = __floats2half2_rn(b.z, b.w);
        uint4 o;
        o.x = *(unsigned*)&h0; o.y = *(unsigned*)&h1;
        o.z = *(unsigned*)&h2; o.w = *(unsigned*)&h3;
        dst[c] = o;
    }
    if (i == 0) g_rowstart[NN] = NE;
}

// ---------------------------------------------------------------------------
// L2: ONE 64-bit atomic per edge: count + fixed-point degree sum; the old
// value's hi bits give this edge's slot within its row (no scatter atomic).
// ---------------------------------------------------------------------------
__global__ void deg_slot_kernel(const int* __restrict__ row, const float* __restrict__ ew) {
    int e = blockIdx.x * blockDim.x + threadIdx.x;
    if (e < NE) {
        unsigned long long v = (1ULL << 40)
            + (unsigned long long)(ew[e] * 4294967296.0f);  // 2^32 fixed point
        unsigned long long old = atomicAdd(&g_packed[row[e]], v);
        g_slot[e] = (int)(old >> 40);
    }
}

// ---------------------------------------------------------------------------
// L3: single-block scan: rowstart = exclusive prefix of counts; also emits
// g_dis = rsqrt(deg). 1024 threads x ceil(NN/1024)=49 elements.
// ---------------------------------------------------------------------------
__global__ void __launch_bounds__(1024) scan_single_kernel() {
    __shared__ int s[1024];
    const int CH = (NN + 1023) / 1024;   // 49
    int t = threadIdx.x;
    int beg = t * CH;
    int end = (beg + CH < NN) ? beg + CH : NN;

    int sum = 0;
    for (int i = beg; i < end; i++) {
        unsigned long long p = g_packed[i];
        sum += (int)(p >> 40);
        float deg = (float)(p & 0xFFFFFFFFFFULL) * (1.0f / 4294967296.0f);
        g_dis[i] = (deg > 0.0f) ? rsqrtf(deg) : 0.0f;
    }
    s[t] = sum;
    __syncthreads();
    for (int off = 1; off < 1024; off <<= 1) {
        int add = (t >= off) ? s[t - off] : 0;
        __syncthreads();
        s[t] += add;
        __syncthreads();
    }
    int run = s[t] - sum;   // exclusive base for this thread's chunk
    for (int i = beg; i < end; i++) {
        unsigned long long p = g_packed[i];
        g_rowstart[i] = run;
        run += (int)(p >> 40);
    }
}

// ---------------------------------------------------------------------------
// L4 (profiled slot): atomic-free scatter into CSR with folded weight:
//   w = -dis[row] * ew * dis[col];  dst = rowstart[row] + slot[e]
// ---------------------------------------------------------------------------
__global__ void scatter_kernel(const int* __restrict__ row, const int* __restrict__ col,
                               const float* __restrict__ ew) {
    int e = blockIdx.x * blockDim.x + threadIdx.x;
    if (e < NE) {
        int r = row[e];
        int c = col[e];
        float w = -__ldg(&g_dis[r]) * ew[e] * __ldg(&g_dis[c]);
        int dst = __ldg(&g_rowstart[r]) + g_slot[e];
        g_ecsr[dst] = make_float2(__int_as_float(c), w);
    }
}

// ---------------------------------------------------------------------------
// Row-centric fp16-gather propagation: 8 threads per node, 16B fp16 each.
// Accumulate fp32, store fp16. Symbols bound only in device code.
// ---------------------------------------------------------------------------
__device__ __forceinline__ void prop_accum_edge(float acc[8], float w, uint4 v) {
    const half2* h = (const half2*)&v;
#pragma unroll
    for (int k = 0; k < 4; k++) {
        float2 f = __half22float2(h[k]);
        acc[2 * k + 0] = fmaf(w, f.x, acc[2 * k + 0]);
        acc[2 * k + 1] = fmaf(w, f.y, acc[2 * k + 1]);
    }
}

__device__ __forceinline__ void prop_impl_h(const uint4* __restrict__ src,
                                            uint4* __restrict__ dst,
                                            int gid) {
    int n = gid >> 3;
    int j = gid & 7;
    if (n >= NN) return;

    int s = __ldg(&g_rowstart[n]);
    int e = __ldg(&g_rowstart[n + 1]);

    float acc[8];
#pragma unroll
    for (int k = 0; k < 8; k++) acc[k] = 0.0f;

    int i = s;
    for (; i + 3 < e; i += 4) {
        float2 p[4];
        uint4 v[4];
#pragma unroll
        for (int u = 0; u < 4; u++) p[u] = __ldg(&g_ecsr[i + u]);
#pragma unroll
        for (int u = 0; u < 4; u++)
            v[u] = __ldg(&src[__float_as_int(p[u].x) * 8 + j]);
#pragma unroll
        for (int u = 0; u < 4; u++) prop_accum_edge(acc, p[u].y, v[u]);
    }
    for (; i < e; i++) {
        float2 p = __ldg(&g_ecsr[i]);
        uint4 v = __ldg(&src[__float_as_int(p.x) * 8 + j]);
        prop_accum_edge(acc, p.y, v);
    }

    half2 h0 = __floats2half2_rn(acc[0], acc[1]);
    half2 h1 = __floats2half2_rn(acc[2], acc[3]);
    half2 h2 = __floats2half2_rn(acc[4], acc[5]);
    half2 h3 = __floats2half2_rn(acc[6], acc[7]);
    uint4 o;
    o.x = *(unsigned*)&h0; o.y = *(unsigned*)&h1;
    o.z = *(unsigned*)&h2; o.w = *(unsigned*)&h3;
    dst[n * 8 + j] = o;
}

__global__ void __launch_bounds__(256) prop1_kernel() {
    int gid = blockIdx.x * blockDim.x + threadIdx.x;
    prop_impl_h((const uint4*)g_xh, (uint4*)g_T1h, gid);
}

__global__ void __launch_bounds__(256) prop2_kernel() {
    int gid = blockIdx.x * blockDim.x + threadIdx.x;
    prop_impl_h((const uint4*)g_T1h, (uint4*)g_P2h, gid);
}

// ---------------------------------------------------------------------------
// Epilogue: out = relu( x@(W0-W2) + T1@W1 + P2@(2*W2) + b )
// x fp32 (exact); T1/P2 fp16. FFMA2 accumulators. 2 nodes x 16 outs/thread.
// ---------------------------------------------------------------------------
__global__ void __launch_bounds__(256) epi_kernel(const float* __restrict__ x,
                                                  const float* __restrict__ W,
                                                  const float* __restrict__ b,
                                                  float* __restrict__ out) {
    __shared__ float ws[192 * 64];  // [W0-W2 ; W1 ; 2*W2], each [64][64]

    int tid = threadIdx.x;
    for (int i = tid; i < 4096; i += 256) {
        float w0 = W[i];
        float w1 = W[4096 + i];
        float w2 = W[8192 + i];
        ws[i]        = w0 - w2;
        ws[4096 + i] = w1;
        ws[8192 + i] = 2.0f * w2;
    }
    __syncthreads();

    int np = tid >> 2;           // 0..63 -> node pair
    int og = tid & 3;            // output group: 16 outputs
    int n0 = blockIdx.x * 128 + np * 2;
    int n1 = n0 + 1;
    if (n0 >= NN) return;
    bool has1 = (n1 < NN);

    unsigned long long acc0[8], acc1[8];   // 16 outputs as 8 f32x2 each
#pragma unroll
    for (int o = 0; o < 8; o++) { acc0[o] = 0ULL; acc1[o] = 0ULL; }

    const float4* a0x = (const float4*)(x + (long long)n0 * CC);
    const float4* a1x = (const float4*)(x + (long long)n1 * CC);

#pragma unroll
    for (int part = 0; part < 3; part++) {
        const uint2* h0p = (part == 1) ? (const uint2*)(g_T1h + n0 * CC)
                                       : (const uint2*)(g_P2h + n0 * CC);
        const uint2* h1p = (part == 1) ? (const uint2*)(g_T1h + n1 * CC)
                                       : (const uint2*)(g_P2h + n1 * CC);
        const float* wsp = ws + part * 4096;
        for (int c4 = 0; c4 < 16; c4++) {
            float av0[4], av1[4];
            if (part == 0) {
                float4 a0 = __ldg(&a0x[c4]);
                av0[0] = a0.x; av0[1] = a0.y; av0[2] = a0.z; av0[3] = a0.w;
                if (has1) {
                    float4 a1 = __ldg(&a1x[c4]);
                    av1[0] = a1.x; av1[1] = a1.y; av1[2] = a1.z; av1[3] = a1.w;
                } else {
                    av1[0] = av1[1] = av1[2] = av1[3] = 0.0f;
                }
            } else {
                uint2 h0 = __ldg(&h0p[c4]);
                float2 f0 = __half22float2(*(const half2*)&h0.x);
                float2 f1 = __half22float2(*(const half2*)&h0.y);
                av0[0] = f0.x; av0[1] = f0.y; av0[2] = f1.x; av0[3] = f1.y;
                if (has1) {
                    uint2 h1 = __ldg(&h1p[c4]);
                    float2 g0 = __half22float2(*(const half2*)&h1.x);
                    float2 g1 = __half22float2(*(const half2*)&h1.y);
                    av1[0] = g0.x; av1[1] = g0.y; av1[2] = g1.x; av1[3] = g1.y;
                } else {
                    av1[0] = av1[1] = av1[2] = av1[3] = 0.0f;
                }
            }
#pragma unroll
            for (int t = 0; t < 4; t++) {
                unsigned long long pa0, pa1;
                PACK2(pa0, av0[t], av0[t]);
                PACK2(pa1, av1[t], av1[t]);
                const ulonglong2* wp =
                    (const ulonglong2*)(wsp + (c4 * 4 + t) * 64 + og * 16);
#pragma unroll
                for (int q = 0; q < 4; q++) {
                    ulonglong2 wv = wp[q];
                    FMA2(acc0[q * 2 + 0], pa0, wv.x);
                    FMA2(acc0[q * 2 + 1], pa0, wv.y);
                    FMA2(acc1[q * 2 + 0], pa1, wv.x);
                    FMA2(acc1[q * 2 + 1], pa1, wv.y);
                }
            }
        }
    }

    int jbase = og * 16;
    float4* outp0 = (float4*)(out + (long long)n0 * CC + jbase);
#pragma unroll
    for (int q = 0; q < 4; q++) {
        float lo0, hi0, lo1, hi1;
        UNPACK2(lo0, hi0, acc0[q * 2 + 0]);
        UNPACK2(lo1, hi1, acc0[q * 2 + 1]);
        float4 r;
        r.x = fmaxf(lo0 + __ldg(&b[jbase + q * 4 + 0]), 0.0f);
        r.y = fmaxf(hi0 + __ldg(&b[jbase + q * 4 + 1]), 0.0f);
        r.z = fmaxf(lo1 + __ldg(&b[jbase + q * 4 + 2]), 0.0f);
        r.w = fmaxf(hi1 + __ldg(&b[jbase + q * 4 + 3]), 0.0f);
        outp0[q] = r;
    }
    if (has1) {
        float4* outp1 = (float4*)(out + (long long)n1 * CC + jbase);
#pragma unroll
        for (int q = 0; q < 4; q++) {
            float lo0, hi0, lo1, hi1;
            UNPACK2(lo0, hi0, acc1[q * 2 + 0]);
            UNPACK2(lo1, hi1, acc1[q * 2 + 1]);
            float4 r;
            r.x = fmaxf(lo0 + __ldg(&b[jbase + q * 4 + 0]), 0.0f);
            r.y = fmaxf(hi0 + __ldg(&b[jbase + q * 4 + 1]), 0.0f);
            r.z = fmaxf(lo1 + __ldg(&b[jbase + q * 4 + 2]), 0.0f);
            r.w = fmaxf(hi1 + __ldg(&b[jbase + q * 4 + 3]), 0.0f);
            outp1[q] = r;
        }
    }
}

// ---------------------------------------------------------------------------
// Launch (7 kernels; scatter is the 4th -> gets profiled)
// ---------------------------------------------------------------------------
extern "C" void kernel_launch(void* const* d_in, const int* in_sizes, int n_in,
                              void* d_out, int out_size) {
    const float* x  = (const float*)d_in[0];   // [N, 64]
    const int*   ei = (const int*)d_in[1];     // [2, E]
    const float* ew = (const float*)d_in[2];   // [E]
    const float* W  = (const float*)d_in[3];   // [3, 64, 64]
    const float* b  = (const float*)d_in[4];   // [64]
    float* out = (float*)d_out;                // [N, 64]

    const int E = in_sizes[2];                 // 800000
    const int* row = ei;
    const int* col = ei + E;

    const int egrid = (NE + 255) / 256;

    zero_convert_kernel<<<1024, 256>>>((const float4*)x);
    deg_slot_kernel<<<egrid, 256>>>(row, ew);
    scan_single_kernel<<<1, 1024>>>();
    scatter_kernel<<<egrid, 256>>>(row, col, ew);

    const int pgrid = (NN * 8 + 255) / 256;
    prop1_kernel<<<pgrid, 256>>>();
    prop2_kernel<<<pgrid, 256>>>();

    epi_kernel<<<(NN + 127) / 128, 256>>>(x, W, b, out);
    (void)E; (void)n_in; (void)out_size;
}

// round 14
// speedup vs baseline: 1.5643x; 1.5643x over previous
#include <cuda_runtime.h>
#include <cuda_fp16.h>

#define NN 50000
#define NE 800000
#define CC 64
#define NBLK ((NN + 255) / 256)   // 196

// ---------------- device scratch (no allocations allowed) ----------------
__device__ float  g_deg[NN];
__device__ int    g_cnt[NN];
__device__ int    g_bsum[NBLK];
__device__ int    g_rowstart[NN + 1];
__device__ int    g_pos[NN];
__device__ float2 g_ecsr[NE];          // {col (bit-cast int), w} sorted by row
__device__ __half g_xh[NN * CC];       // fp16 copy of x (gather source)
__device__ __half g_T1h[NN * CC];      // T1 = L_hat @ x      (fp16)
__device__ __half g_P2h[NN * CC];      // P2 = L_hat @ T1     (fp16)

// Packed fp32x2 FMA (sm_103a FFMA2 — only reachable via PTX)
#define FMA2(d, a, b) \
    asm("fma.rn.f32x2 %0, %1, %2, %0;" : "+l"(d) : "l"(a), "l"(b))
#define PACK2(d, lo, hi) \
    asm("mov.b64 %0, {%1, %2};" : "=l"(d) : "f"(lo), "f"(hi))
#define UNPACK2(lo, hi, s) \
    asm("mov.b64 {%0, %1}, %2;" : "=f"(lo), "=f"(hi) : "l"(s))

// ---------------------------------------------------------------------------
// Zero deg/cnt, set sentinel, and convert x -> fp16 (fused; independent work)
// ---------------------------------------------------------------------------
__global__ void zero_convert_kernel(const float4* __restrict__ x) {
    int i = blockIdx.x * blockDim.x + threadIdx.x;
    int stride = gridDim.x * blockDim.x;
    for (int j = i; j < NN; j += stride) {
        g_deg[j] = 0.0f;
        g_cnt[j] = 0;
    }
    const int chunks = NN * CC / 8;   // 400000
    uint4* dst = (uint4*)g_xh;
    for (int c = i; c < chunks; c += stride) {
        float4 a = __ldg(&x[c * 2 + 0]);
        float4 b = __ldg(&x[c * 2 + 1]);
        half2 h0 = __floats2half2_rn(a.x, a.y);
        half2 h1 = __floats2half2_rn(a.z, a.w);
        half2 h2 = __floats2half2_rn(b.x, b.y);
        half2 h3 = __floats2half2_rn(b.z, b.w);
        uint4 o;
        o.x = *(unsigned*)&h0; o.y = *(unsigned*)&h1;
        o.z = *(unsigned*)&h2; o.w = *(unsigned*)&h3;
        dst[c] = o;
    }
    if (i == 0) g_rowstart[NN] = NE;
}

// ---------------------------------------------------------------------------
// deg[r] += ew ; cnt[r] += 1   (fire-and-forget REDs — proven fast)
// ---------------------------------------------------------------------------
__global__ void deg_kernel(const int* __restrict__ row, const float* __restrict__ ew) {
    int e = blockIdx.x * blockDim.x + threadIdx.x;
    if (e < NE) {
        int r = row[e];
        atomicAdd(&g_deg[r], ew[e]);
        atomicAdd(&g_cnt[r], 1);
    }
}

// ---------------------------------------------------------------------------
// Scan step 1: per-block sums of cnt
// ---------------------------------------------------------------------------
__global__ void scan1_kernel() {
    __shared__ int s[256];
    int t = threadIdx.x;
    int idx = blockIdx.x * 256 + t;
    s[t] = (idx < NN) ? g_cnt[idx] : 0;
    __syncthreads();
    for (int off = 128; off > 0; off >>= 1) {
        if (t < off) s[t] += s[t + off];
        __syncthreads();
    }
    if (t == 0) g_bsum[blockIdx.x] = s[0];
}

// ---------------------------------------------------------------------------
// Scan step 2 (fused spine + local exclusive scan)
// ---------------------------------------------------------------------------
__global__ void scan2_kernel() {
    __shared__ int s[256];
    __shared__ int base_sh;
    int t = threadIdx.x;
    int idx = blockIdx.x * 256 + t;

    int part = 0;
    for (int j = t; j < blockIdx.x; j += 256) part += g_bsum[j];
    s[t] = part;
    __syncthreads();
    for (int off = 128; off > 0; off >>= 1) {
        if (t < off) s[t] += s[t + off];
        __syncthreads();
    }
    if (t == 0) base_sh = s[0];
    __syncthreads();
    int base = base_sh;
    __syncthreads();

    int v = (idx < NN) ? g_cnt[idx] : 0;
    s[t] = v;
    __syncthreads();
    for (int off = 1; off < 256; off <<= 1) {
        int add = (t >= off) ? s[t - off] : 0;
        __syncthreads();
        s[t] += add;
        __syncthreads();
    }
    if (idx < NN) {
        int excl = s[t] - v + base;
        g_rowstart[idx] = excl;
        g_pos[idx] = excl;
    }
}

// ---------------------------------------------------------------------------
// Scatter edges into CSR with normalized Laplacian weight folded in
// (ATOM.32-with-return — proven ~15us in R12)
// ---------------------------------------------------------------------------
__global__ void scatter_kernel(const int* __restrict__ row, const int* __restrict__ col,
                               const float* __restrict__ ew) {
    int e = blockIdx.x * blockDim.x + threadIdx.x;
    if (e < NE) {
        int r = row[e];
        int c = col[e];
        float dr = __ldg(&g_deg[r]);
        float dc = __ldg(&g_deg[c]);
        float ir = (dr > 0.0f) ? rsqrtf(dr) : 0.0f;
        float ic = (dc > 0.0f) ? rsqrtf(dc) : 0.0f;
        float w = -ir * ew[e] * ic;
        int slot = atomicAdd(&g_pos[r], 1);
        g_ecsr[slot] = make_float2(__int_as_float(c), w);
    }
}

// ---------------------------------------------------------------------------
// Row-centric fp16-gather propagation: 8 threads per node, 16B fp16 each.
// Accumulate fp32, store fp16. Symbols bound only in device code.
// ---------------------------------------------------------------------------
__device__ __forceinline__ void prop_accum_edge(float acc[8], float w, uint4 v) {
    const half2* h = (const half2*)&v;
#pragma unroll
    for (int k = 0; k < 4; k++) {
        float2 f = __half22float2(h[k]);
        acc[2 * k + 0] = fmaf(w, f.x, acc[2 * k + 0]);
        acc[2 * k + 1] = fmaf(w, f.y, acc[2 * k + 1]);
    }
}

__device__ __forceinline__ void prop_impl_h(const uint4* __restrict__ src,
                                            uint4* __restrict__ dst,
                                            int gid) {
    int n = gid >> 3;
    int j = gid & 7;
    if (n >= NN) return;

    int s = __ldg(&g_rowstart[n]);
    int e = __ldg(&g_rowstart[n + 1]);

    float acc[8];
#pragma unroll
    for (int k = 0; k < 8; k++) acc[k] = 0.0f;

    int i = s;
    for (; i + 3 < e; i += 4) {
        float2 p[4];
        uint4 v[4];
#pragma unroll
        for (int u = 0; u < 4; u++) p[u] = __ldg(&g_ecsr[i + u]);
#pragma unroll
        for (int u = 0; u < 4; u++)
            v[u] = __ldg(&src[__float_as_int(p[u].x) * 8 + j]);
#pragma unroll
        for (int u = 0; u < 4; u++) prop_accum_edge(acc, p[u].y, v[u]);
    }
    for (; i < e; i++) {
        float2 p = __ldg(&g_ecsr[i]);
        uint4 v = __ldg(&src[__float_as_int(p.x) * 8 + j]);
        prop_accum_edge(acc, p.y, v);
    }

    half2 h0 = __floats2half2_rn(acc[0], acc[1]);
    half2 h1 = __floats2half2_rn(acc[2], acc[3]);
    half2 h2 = __floats2half2_rn(acc[4], acc[5]);
    half2 h3 = __floats2half2_rn(acc[6], acc[7]);
    uint4 o;
    o.x = *(unsigned*)&h0; o.y = *(unsigned*)&h1;
    o.z = *(unsigned*)&h2; o.w = *(unsigned*)&h3;
    dst[n * 8 + j] = o;
}

__global__ void __launch_bounds__(256) prop1_kernel() {
    int gid = blockIdx.x * blockDim.x + threadIdx.x;
    prop_impl_h((const uint4*)g_xh, (uint4*)g_T1h, gid);
}

__global__ void __launch_bounds__(256) prop2_kernel() {
    int gid = blockIdx.x * blockDim.x + threadIdx.x;
    prop_impl_h((const uint4*)g_T1h, (uint4*)g_P2h, gid);
}

// ---------------------------------------------------------------------------
// Epilogue: out = relu( x@(W0-W2) + T1@W1 + P2@(2*W2) + b )
// ALL activations read fp16 (x via g_xh) — uniform load path, no branch.
// FFMA2 accumulators. 2 nodes x 16 outputs per thread.
// ---------------------------------------------------------------------------
__global__ void __launch_bounds__(256) epi_kernel(const float* __restrict__ W,
                                                  const float* __restrict__ b,
                                                  float* __restrict__ out) {
    __shared__ float ws[192 * 64];  // [W0-W2 ; W1 ; 2*W2], each [64][64]

    int tid = threadIdx.x;
    for (int i = tid; i < 4096; i += 256) {
        float w0 = W[i];
        float w1 = W[4096 + i];
        float w2 = W[8192 + i];
        ws[i]        = w0 - w2;
        ws[4096 + i] = w1;
        ws[8192 + i] = 2.0f * w2;
    }
    __syncthreads();

    int np = tid >> 2;           // 0..63 -> node pair
    int og = tid & 3;            // output group: 16 outputs
    int n0 = blockIdx.x * 128 + np * 2;
    int n1 = n0 + 1;
    if (n0 >= NN) return;
    bool has1 = (n1 < NN);

    unsigned long long acc0[8], acc1[8];   // 16 outputs as 8 f32x2 each
#pragma unroll
    for (int o = 0; o < 8; o++) { acc0[o] = 0ULL; acc1[o] = 0ULL; }

    const __half* srcs[3] = {g_xh, g_T1h, g_P2h};

#pragma unroll
    for (int part = 0; part < 3; part++) {
        const uint2* h0p = (const uint2*)(srcs[part] + n0 * CC);
        const uint2* h1p = (const uint2*)(srcs[part] + n1 * CC);
        const float* wsp = ws + part * 4096;
        for (int c4 = 0; c4 < 16; c4++) {
            uint2 h0 = __ldg(&h0p[c4]);
            float2 f0 = __half22float2(*(const half2*)&h0.x);
            float2 f1 = __half22float2(*(const half2*)&h0.y);
            float av0[4] = {f0.x, f0.y, f1.x, f1.y};
            float av1[4] = {0.f, 0.f, 0.f, 0.f};
            if (has1) {
                uint2 h1 = __ldg(&h1p[c4]);
                float2 g0 = __half22float2(*(const half2*)&h1.x);
                float2 g1 = __half22float2(*(const half2*)&h1.y);
                av1[0] = g0.x; av1[1] = g0.y; av1[2] = g1.x; av1[3] = g1.y;
            }
#pragma unroll
            for (int t = 0; t < 4; t++) {
                unsigned long long pa0, pa1;
                PACK2(pa0, av0[t], av0[t]);
                PACK2(pa1, av1[t], av1[t]);
                const ulonglong2* wp =
                    (const ulonglong2*)(wsp + (c4 * 4 + t) * 64 + og * 16);
#pragma unroll
                for (int q = 0; q < 4; q++) {
                    ulonglong2 wv = wp[q];
                    FMA2(acc0[q * 2 + 0], pa0, wv.x);
                    FMA2(acc0[q * 2 + 1], pa0, wv.y);
                    FMA2(acc1[q * 2 + 0], pa1, wv.x);
                    FMA2(acc1[q * 2 + 1], pa1, wv.y);
                }
            }
        }
    }

    int jbase = og * 16;
    float4* outp0 = (float4*)(out + (long long)n0 * CC + jbase);
#pragma unroll
    for (int q = 0; q < 4; q++) {
        float lo0, hi0, lo1, hi1;
        UNPACK2(lo0, hi0, acc0[q * 2 + 0]);
        UNPACK2(lo1, hi1, acc0[q * 2 + 1]);
        float4 r;
        r.x = fmaxf(lo0 + __ldg(&b[jbase + q * 4 + 0]), 0.0f);
        r.y = fmaxf(hi0 + __ldg(&b[jbase + q * 4 + 1]), 0.0f);
        r.z = fmaxf(lo1 + __ldg(&b[jbase + q * 4 + 2]), 0.0f);
        r.w = fmaxf(hi1 + __ldg(&b[jbase + q * 4 + 3]), 0.0f);
        outp0[q] = r;
    }
    if (has1) {
        float4* outp1 = (float4*)(out + (long long)n1 * CC + jbase);
#pragma unroll
        for (int q = 0; q < 4; q++) {
            float lo0, hi0, lo1, hi1;
            UNPACK2(lo0, hi0, acc1[q * 2 + 0]);
            UNPACK2(lo1, hi1, acc1[q * 2 + 1]);
            float4 r;
            r.x = fmaxf(lo0 + __ldg(&b[jbase + q * 4 + 0]), 0.0f);
            r.y = fmaxf(hi0 + __ldg(&b[jbase + q * 4 + 1]), 0.0f);
            r.z = fmaxf(lo1 + __ldg(&b[jbase + q * 4 + 2]), 0.0f);
            r.w = fmaxf(hi1 + __ldg(&b[jbase + q * 4 + 3]), 0.0f);
            outp1[q] = r;
        }
    }
}

// ---------------------------------------------------------------------------
// Launch (R12 structure restored)
// ---------------------------------------------------------------------------
extern "C" void kernel_launch(void* const* d_in, const int* in_sizes, int n_in,
                              void* d_out, int out_size) {
    const float* x  = (const float*)d_in[0];   // [N, 64]
    const int*   ei = (const int*)d_in[1];     // [2, E]
    const float* ew = (const float*)d_in[2];   // [E]
    const float* W  = (const float*)d_in[3];   // [3, 64, 64]
    const float* b  = (const float*)d_in[4];   // [64]
    float* out = (float*)d_out;                // [N, 64]

    const int E = in_sizes[2];                 // 800000
    const int* row = ei;
    const int* col = ei + E;

    const int egrid = (NE + 255) / 256;

    zero_convert_kernel<<<1024, 256>>>((const float4*)x);
    deg_kernel<<<egrid, 256>>>(row, ew);
    scan1_kernel<<<NBLK, 256>>>();
    scan2_kernel<<<NBLK, 256>>>();
    scatter_kernel<<<egrid, 256>>>(row, col, ew);

    const int pgrid = (NN * 8 + 255) / 256;
    prop1_kernel<<<pgrid, 256>>>();
    prop2_kernel<<<pgrid, 256>>>();

    epi_kernel<<<(NN + 127) / 128, 256>>>(W, b, out);
    (void)E; (void)n_in; (void)out_size;
}

// round 15
// speedup vs baseline: 1.7304x; 1.1062x over previous
#include <cuda_runtime.h>
#include <cuda_fp16.h>

#define NN 50000
#define NE 800000
#define CC 64
#define NBLK ((NN + 255) / 256)   // 196

// ---------------- device scratch (no allocations allowed) ----------------
__device__ float  g_deg[NN];
__device__ int    g_cnt[NN];
__device__ int    g_rowstart[NN + 1];
__device__ int    g_pos[NN];
__device__ float2 g_ecsr[NE];          // {col (bit-cast int), w} sorted by row
__device__ __half g_xh[NN * CC];       // fp16 copy of x (gather source)
__device__ __half g_T1h[NN * CC];      // T1 = L_hat @ x      (fp16)
__device__ __half g_P2h[NN * CC];      // P2 = L_hat @ T1     (fp16)

// Packed fp32x2 FMA (sm_103a FFMA2 — only reachable via PTX)
#define FMA2(d, a, b) \
    asm("fma.rn.f32x2 %0, %1, %2, %0;" : "+l"(d) : "l"(a), "l"(b))
#define PACK2(d, lo, hi) \
    asm("mov.b64 %0, {%1, %2};" : "=l"(d) : "f"(lo), "f"(hi))
#define UNPACK2(lo, hi, s) \
    asm("mov.b64 {%0, %1}, %2;" : "=f"(lo), "=f"(hi) : "l"(s))

// ---------------------------------------------------------------------------
// Zero deg/cnt, set sentinel, and convert x -> fp16 (fused; independent work)
// ---------------------------------------------------------------------------
__global__ void zero_convert_kernel(const float4* __restrict__ x) {
    int i = blockIdx.x * blockDim.x + threadIdx.x;
    int stride = gridDim.x * blockDim.x;
    for (int j = i; j < NN; j += stride) {
        g_deg[j] = 0.0f;
        g_cnt[j] = 0;
    }
    const int chunks = NN * CC / 8;   // 400000
    uint4* dst = (uint4*)g_xh;
    for (int c = i; c < chunks; c += stride) {
        float4 a = __ldg(&x[c * 2 + 0]);
        float4 b = __ldg(&x[c * 2 + 1]);
        half2 h0 = __floats2half2_rn(a.x, a.y);
        half2 h1 = __floats2half2_rn(a.z, a.w);
        half2 h2 = __floats2half2_rn(b.x, b.y);
        half2 h3 = __floats2half2_rn(b.z, b.w);
        uint4 o;
        o.x = *(unsigned*)&h0; o.y = *(unsigned*)&h1;
        o.z = *(unsigned*)&h2; o.w = *(unsigned*)&h3;
        dst[c] = o;
    }
    if (i == 0) g_rowstart[NN] = NE;
}

// ---------------------------------------------------------------------------
// deg[r] += ew ; cnt[r] += 1   (fire-and-forget RED.32s — proven fast)
// ---------------------------------------------------------------------------
__global__ void deg_kernel(const int* __restrict__ row, const float* __restrict__ ew) {
    int e = blockIdx.x * blockDim.x + threadIdx.x;
    if (e < NE) {
        int r = row[e];
        atomicAdd(&g_deg[r], ew[e]);
        atomicAdd(&g_cnt[r], 1);
    }
}

// ---------------------------------------------------------------------------
// Fused single-pass scan: each block sums cnt[0..blockStart) itself (cheap,
// <=50k ints), then local exclusive scan -> rowstart/pos. One launch.
// ---------------------------------------------------------------------------
__global__ void scan_kernel() {
    __shared__ int s[256];
    __shared__ int base_sh;
    int t = threadIdx.x;
    int blockStart = blockIdx.x * 256;

    int part = 0;
    for (int j = t; j < blockStart; j += 256) part += g_cnt[j];
    s[t] = part;
    __syncthreads();
    for (int off = 128; off > 0; off >>= 1) {
        if (t < off) s[t] += s[t + off];
        __syncthreads();
    }
    if (t == 0) base_sh = s[0];
    __syncthreads();
    int base = base_sh;
    __syncthreads();

    int idx = blockStart + t;
    int v = (idx < NN) ? g_cnt[idx] : 0;
    s[t] = v;
    __syncthreads();
    for (int off = 1; off < 256; off <<= 1) {
        int add = (t >= off) ? s[t - off] : 0;
        __syncthreads();
        s[t] += add;
        __syncthreads();
    }
    if (idx < NN) {
        int excl = s[t] - v + base;
        g_rowstart[idx] = excl;
        g_pos[idx] = excl;
    }
}

// ---------------------------------------------------------------------------
// Scatter edges into CSR with normalized Laplacian weight folded in
// (ATOM.32-with-return — measured ~15us)
// ---------------------------------------------------------------------------
__global__ void scatter_kernel(const int* __restrict__ row, const int* __restrict__ col,
                               const float* __restrict__ ew) {
    int e = blockIdx.x * blockDim.x + threadIdx.x;
    if (e < NE) {
        int r = row[e];
        int c = col[e];
        float dr = __ldg(&g_deg[r]);
        float dc = __ldg(&g_deg[c]);
        float ir = (dr > 0.0f) ? rsqrtf(dr) : 0.0f;
        float ic = (dc > 0.0f) ? rsqrtf(dc) : 0.0f;
        float w = -ir * ew[e] * ic;
        int slot = atomicAdd(&g_pos[r], 1);
        g_ecsr[slot] = make_float2(__int_as_float(c), w);
    }
}

// ---------------------------------------------------------------------------
// Row-centric fp16-gather propagation: 8 threads per node, 16B fp16 each.
// Accumulate fp32, store fp16. Symbols bound only in device code.
// ---------------------------------------------------------------------------
__device__ __forceinline__ void prop_accum_edge(float acc[8], float w, uint4 v) {
    const half2* h = (const half2*)&v;
#pragma unroll
    for (int k = 0; k < 4; k++) {
        float2 f = __half22float2(h[k]);
        acc[2 * k + 0] = fmaf(w, f.x, acc[2 * k + 0]);
        acc[2 * k + 1] = fmaf(w, f.y, acc[2 * k + 1]);
    }
}

__device__ __forceinline__ void prop_impl_h(const uint4* __restrict__ src,
                                            uint4* __restrict__ dst,
                                            int gid) {
    int n = gid >> 3;
    int j = gid & 7;
    if (n >= NN) return;

    int s = __ldg(&g_rowstart[n]);
    int e = __ldg(&g_rowstart[n + 1]);

    float acc[8];
#pragma unroll
    for (int k = 0; k < 8; k++) acc[k] = 0.0f;

    int i = s;
    for (; i + 3 < e; i += 4) {
        float2 p[4];
        uint4 v[4];
#pragma unroll
        for (int u = 0; u < 4; u++) p[u] = __ldg(&g_ecsr[i + u]);
#pragma unroll
        for (int u = 0; u < 4; u++)
            v[u] = __ldg(&src[__float_as_int(p[u].x) * 8 + j]);
#pragma unroll
        for (int u = 0; u < 4; u++) prop_accum_edge(acc, p[u].y, v[u]);
    }
    for (; i < e; i++) {
        float2 p = __ldg(&g_ecsr[i]);
        uint4 v = __ldg(&src[__float_as_int(p.x) * 8 + j]);
        prop_accum_edge(acc, p.y, v);
    }

    half2 h0 = __floats2half2_rn(acc[0], acc[1]);
    half2 h1 = __floats2half2_rn(acc[2], acc[3]);
    half2 h2 = __floats2half2_rn(acc[4], acc[5]);
    half2 h3 = __floats2half2_rn(acc[6], acc[7]);
    uint4 o;
    o.x = *(unsigned*)&h0; o.y = *(unsigned*)&h1;
    o.z = *(unsigned*)&h2; o.w = *(unsigned*)&h3;
    dst[n * 8 + j] = o;
}

__global__ void __launch_bounds__(256) prop1_kernel() {
    int gid = blockIdx.x * blockDim.x + threadIdx.x;
    prop_impl_h((const uint4*)g_xh, (uint4*)g_T1h, gid);
}

__global__ void __launch_bounds__(256) prop2_kernel() {
    int gid = blockIdx.x * blockDim.x + threadIdx.x;
    prop_impl_h((const uint4*)g_T1h, (uint4*)g_P2h, gid);
}

// ---------------------------------------------------------------------------
// Epilogue: out = relu( x@(W0-W2) + T1@W1 + P2@(2*W2) + b )
// 4 nodes x 16 outputs per thread (W shared-loads amortized over 4 nodes:
// the kernel is LDS-bound, this halves LDS traffic per node). FFMA2 accum.
// NN % 4 == 0 so a block's 4-node groups need no per-node guard.
// ---------------------------------------------------------------------------
__global__ void __launch_bounds__(256) epi_kernel(const float* __restrict__ W,
                                                  const float* __restrict__ b,
                                                  float* __restrict__ out) {
    __shared__ float ws[192 * 64];  // [W0-W2 ; W1 ; 2*W2], each [64][64]

    int tid = threadIdx.x;
    for (int i = tid; i < 4096; i += 256) {
        float w0 = W[i];
        float w1 = W[4096 + i];
        float w2 = W[8192 + i];
        ws[i]        = w0 - w2;
        ws[4096 + i] = w1;
        ws[8192 + i] = 2.0f * w2;
    }
    __syncthreads();

    int ng = tid >> 2;           // 0..63 -> group of 4 nodes
    int og = tid & 3;            // output group: 16 outputs
    int nb = blockIdx.x * 256 + ng * 4;
    if (nb >= NN) return;        // NN%4==0: either all 4 valid or none

    unsigned long long acc[4][8];   // 4 nodes x 16 outputs (8 f32x2)
#pragma unroll
    for (int k = 0; k < 4; k++)
#pragma unroll
        for (int o = 0; o < 8; o++) acc[k][o] = 0ULL;

    const __half* srcs[3] = {g_xh, g_T1h, g_P2h};

#pragma unroll
    for (int part = 0; part < 3; part++) {
        const uint2* hp = (const uint2*)(srcs[part] + (long long)nb * CC);
        const float* wsp = ws + part * 4096;
        for (int c4 = 0; c4 < 16; c4++) {
            float av[4][4];
#pragma unroll
            for (int k = 0; k < 4; k++) {
                uint2 h = __ldg(&hp[k * 16 + c4]);
                float2 f0 = __half22float2(*(const half2*)&h.x);
                float2 f1 = __half22float2(*(const half2*)&h.y);
                av[k][0] = f0.x; av[k][1] = f0.y; av[k][2] = f1.x; av[k][3] = f1.y;
            }
#pragma unroll
            for (int t = 0; t < 4; t++) {
                unsigned long long pa[4];
#pragma unroll
                for (int k = 0; k < 4; k++) PACK2(pa[k], av[k][t], av[k][t]);
                const ulonglong2* wp =
                    (const ulonglong2*)(wsp + (c4 * 4 + t) * 64 + og * 16);
#pragma unroll
                for (int q = 0; q < 4; q++) {
                    ulonglong2 wv = wp[q];
#pragma unroll
                    for (int k = 0; k < 4; k++) {
                        FMA2(acc[k][q * 2 + 0], pa[k], wv.x);
                        FMA2(acc[k][q * 2 + 1], pa[k], wv.y);
                    }
                }
            }
        }
    }

    int jbase = og * 16;
    float bb[16];
#pragma unroll
    for (int o = 0; o < 16; o++) bb[o] = __ldg(&b[jbase + o]);

#pragma unroll
    for (int k = 0; k < 4; k++) {
        float4* outp = (float4*)(out + (long long)(nb + k) * CC + jbase);
#pragma unroll
        for (int q = 0; q < 4; q++) {
            float lo0, hi0, lo1, hi1;
            UNPACK2(lo0, hi0, acc[k][q * 2 + 0]);
            UNPACK2(lo1, hi1, acc[k][q * 2 + 1]);
            float4 r;
            r.x = fmaxf(lo0 + bb[q * 4 + 0], 0.0f);
            r.y = fmaxf(hi0 + bb[q * 4 + 1], 0.0f);
            r.z = fmaxf(lo1 + bb[q * 4 + 2], 0.0f);
            r.w = fmaxf(hi1 + bb[q * 4 + 3], 0.0f);
            outp[q] = r;
        }
    }
}

// ---------------------------------------------------------------------------
// Launch (7 kernels)
// ---------------------------------------------------------------------------
extern "C" void kernel_launch(void* const* d_in, const int* in_sizes, int n_in,
                              void* d_out, int out_size) {
    const float* x  = (const float*)d_in[0];   // [N, 64]
    const int*   ei = (const int*)d_in[1];     // [2, E]
    const float* ew = (const float*)d_in[2];   // [E]
    const float* W  = (const float*)d_in[3];   // [3, 64, 64]
    const float* b  = (const float*)d_in[4];   // [64]
    float* out = (float*)d_out;                // [N, 64]

    const int E = in_sizes[2];                 // 800000
    const int* row = ei;
    const int* col = ei + E;

    const int egrid = (NE + 255) / 256;

    zero_convert_kernel<<<1024, 256>>>((const float4*)x);
    deg_kernel<<<egrid, 256>>>(row, ew);
    scan_kernel<<<NBLK, 256>>>();
    scatter_kernel<<<egrid, 256>>>(row, col, ew);

    const int pgrid = (NN * 8 + 255) / 256;
    prop1_kernel<<<pgrid, 256>>>();
    prop2_kernel<<<pgrid, 256>>>();

    epi_kernel<<<(NN + 255) / 256, 256>>>(W, b, out);
    (void)E; (void)n_in; (void)out_size;
}

// round 16
// speedup vs baseline: 1.7349x; 1.0026x over previous
#include <cuda_runtime.h>
#include <cuda_fp16.h>

#define NN 50000
#define NE 800000
#define CC 64
#define NBLK ((NN + 255) / 256)   // 196
#define NCHUNK (NN * CC / 8)      // 400000 convert chunks

// ---------------- device scratch (no allocations allowed) ----------------
// Zero-initialized at module load; scatter_convert re-zeros cnt/deg at the
// end of every run, so every graph replay starts from zeros (self-cleaning).
__device__ float  g_deg[NN];
__device__ float  g_dis[NN];           // rsqrt(deg) or 0 (written by scan)
__device__ int    g_cnt[NN];
__device__ int    g_rowstart[NN + 1];
__device__ int    g_pos[NN];
__device__ float2 g_ecsr[NE];          // {col (bit-cast int), w} sorted by row
__device__ __half g_xh[NN * CC];       // fp16 copy of x (gather source)
__device__ __half g_T1h[NN * CC];      // T1 = L_hat @ x      (fp16)
__device__ __half g_P2h[NN * CC];      // P2 = L_hat @ T1     (fp16)

// Packed fp32x2 FMA (sm_103a FFMA2 — only reachable via PTX)
#define FMA2(d, a, b) \
    asm("fma.rn.f32x2 %0, %1, %2, %0;" : "+l"(d) : "l"(a), "l"(b))
#define PACK2(d, lo, hi) \
    asm("mov.b64 %0, {%1, %2};" : "=l"(d) : "f"(lo), "f"(hi))
#define UNPACK2(lo, hi, s) \
    asm("mov.b64 {%0, %1}, %2;" : "=f"(lo), "=f"(hi) : "l"(s))

// ---------------------------------------------------------------------------
// L1: deg[r] += ew ; cnt[r] += 1  (cnt/deg are zero on entry: module-load
// zeros on run 1, scatter_convert's cleanup on every later run)
// ---------------------------------------------------------------------------
__global__ void deg_kernel(const int* __restrict__ row, const float* __restrict__ ew) {
    int e = blockIdx.x * blockDim.x + threadIdx.x;
    if (e < NE) {
        int r = row[e];
        atomicAdd(&g_deg[r], ew[e]);
        atomicAdd(&g_cnt[r], 1);
    }
}

// ---------------------------------------------------------------------------
// L2: fused scan: block sums its prefix of cnt, local exclusive scan ->
// rowstart/pos; also emits dis = rsqrt(deg) and the sentinel.
// ---------------------------------------------------------------------------
__global__ void scan_kernel() {
    __shared__ int s[256];
    __shared__ int base_sh;
    int t = threadIdx.x;
    int blockStart = blockIdx.x * 256;

    int part = 0;
    for (int j = t; j < blockStart; j += 256) part += g_cnt[j];
    s[t] = part;
    __syncthreads();
    for (int off = 128; off > 0; off >>= 1) {
        if (t < off) s[t] += s[t + off];
        __syncthreads();
    }
    if (t == 0) base_sh = s[0];
    __syncthreads();
    int base = base_sh;
    __syncthreads();

    int idx = blockStart + t;
    int v = (idx < NN) ? g_cnt[idx] : 0;
    s[t] = v;
    __syncthreads();
    for (int off = 1; off < 256; off <<= 1) {
        int add = (t >= off) ? s[t - off] : 0;
        __syncthreads();
        s[t] += add;
        __syncthreads();
    }
    if (idx < NN) {
        int excl = s[t] - v + base;
        g_rowstart[idx] = excl;
        g_pos[idx] = excl;
        float d = g_deg[idx];
        g_dis[idx] = (d > 0.0f) ? rsqrtf(d) : 0.0f;
    }
    if (blockIdx.x == 0 && t == 0) g_rowstart[NN] = NE;
}

// ---------------------------------------------------------------------------
// L3: scatter into CSR (+ fused x->fp16 convert + cnt/deg cleanup).
//   w = -dis[row] * ew * dis[col];  slot from ATOM.32-return on pos.
// ---------------------------------------------------------------------------
__global__ void scatter_convert_kernel(const int* __restrict__ row,
                                       const int* __restrict__ col,
                                       const float* __restrict__ ew,
                                       const float4* __restrict__ x) {
    int e = blockIdx.x * blockDim.x + threadIdx.x;
    if (e < NE) {
        int r = row[e];
        int c = col[e];
        float w = -__ldg(&g_dis[r]) * ew[e] * __ldg(&g_dis[c]);
        int slot = atomicAdd(&g_pos[r], 1);
        g_ecsr[slot] = make_float2(__int_as_float(c), w);
    }
    // fused fp16 convert of x (independent; must finish before prop1 -> same
    // kernel boundary provides the ordering)
    if (e < NCHUNK) {
        float4 a = __ldg(&x[e * 2 + 0]);
        float4 bq = __ldg(&x[e * 2 + 1]);
        half2 h0 = __floats2half2_rn(a.x, a.y);
        half2 h1 = __floats2half2_rn(a.z, a.w);
        half2 h2 = __floats2half2_rn(bq.x, bq.y);
        half2 h3 = __floats2half2_rn(bq.z, bq.w);
        uint4 o;
        o.x = *(unsigned*)&h0; o.y = *(unsigned*)&h1;
        o.z = *(unsigned*)&h2; o.w = *(unsigned*)&h3;
        ((uint4*)g_xh)[e] = o;
    }
    // self-cleaning: restore cnt/deg to zero for the next replay
    if (e < NN) {
        g_cnt[e] = 0;
        g_deg[e] = 0.0f;
    }
}

// ---------------------------------------------------------------------------
// L4 (profiled slot): row-centric fp16-gather propagation.
// 8 threads per node, 16B fp16 each. Accumulate fp32, store fp16.
// ---------------------------------------------------------------------------
__device__ __forceinline__ void prop_accum_edge(float acc[8], float w, uint4 v) {
    const half2* h = (const half2*)&v;
#pragma unroll
    for (int k = 0; k < 4; k++) {
        float2 f = __half22float2(h[k]);
        acc[2 * k + 0] = fmaf(w, f.x, acc[2 * k + 0]);
        acc[2 * k + 1] = fmaf(w, f.y, acc[2 * k + 1]);
    }
}

__device__ __forceinline__ void prop_impl_h(const uint4* __restrict__ src,
                                            uint4* __restrict__ dst,
                                            int gid) {
    int n = gid >> 3;
    int j = gid & 7;
    if (n >= NN) return;

    int s = __ldg(&g_rowstart[n]);
    int e = __ldg(&g_rowstart[n + 1]);

    float acc[8];
#pragma unroll
    for (int k = 0; k < 8; k++) acc[k] = 0.0f;

    int i = s;
    for (; i + 3 < e; i += 4) {
        float2 p[4];
        uint4 v[4];
#pragma unroll
        for (int u = 0; u < 4; u++) p[u] = __ldg(&g_ecsr[i + u]);
#pragma unroll
        for (int u = 0; u < 4; u++)
            v[u] = __ldg(&src[__float_as_int(p[u].x) * 8 + j]);
#pragma unroll
        for (int u = 0; u < 4; u++) prop_accum_edge(acc, p[u].y, v[u]);
    }
    for (; i < e; i++) {
        float2 p = __ldg(&g_ecsr[i]);
        uint4 v = __ldg(&src[__float_as_int(p.x) * 8 + j]);
        prop_accum_edge(acc, p.y, v);
    }

    half2 h0 = __floats2half2_rn(acc[0], acc[1]);
    half2 h1 = __floats2half2_rn(acc[2], acc[3]);
    half2 h2 = __floats2half2_rn(acc[4], acc[5]);
    half2 h3 = __floats2half2_rn(acc[6], acc[7]);
    uint4 o;
    o.x = *(unsigned*)&h0; o.y = *(unsigned*)&h1;
    o.z = *(unsigned*)&h2; o.w = *(unsigned*)&h3;
    dst[n * 8 + j] = o;
}

__global__ void __launch_bounds__(256) prop1_kernel() {
    int gid = blockIdx.x * blockDim.x + threadIdx.x;
    prop_impl_h((const uint4*)g_xh, (uint4*)g_T1h, gid);
}

__global__ void __launch_bounds__(256) prop2_kernel() {
    int gid = blockIdx.x * blockDim.x + threadIdx.x;
    prop_impl_h((const uint4*)g_T1h, (uint4*)g_P2h, gid);
}

// ---------------------------------------------------------------------------
// Epilogue: out = relu( x@(W0-W2) + T1@W1 + P2@(2*W2) + b )
// 4 nodes x 16 outputs per thread; FFMA2; W staged in shared.
// ---------------------------------------------------------------------------
__global__ void __launch_bounds__(256) epi_kernel(const float* __restrict__ W,
                                                  const float* __restrict__ b,
                                                  float* __restrict__ out) {
    __shared__ float ws[192 * 64];  // [W0-W2 ; W1 ; 2*W2], each [64][64]

    int tid = threadIdx.x;
    for (int i = tid; i < 4096; i += 256) {
        float w0 = W[i];
        float w1 = W[4096 + i];
        float w2 = W[8192 + i];
        ws[i]        = w0 - w2;
        ws[4096 + i] = w1;
        ws[8192 + i] = 2.0f * w2;
    }
    __syncthreads();

    int ng = tid >> 2;           // 0..63 -> group of 4 nodes
    int og = tid & 3;            // output group: 16 outputs
    int nb = blockIdx.x * 256 + ng * 4;
    if (nb >= NN) return;        // NN%4==0

    unsigned long long acc[4][8];
#pragma unroll
    for (int k = 0; k < 4; k++)
#pragma unroll
        for (int o = 0; o < 8; o++) acc[k][o] = 0ULL;

    const __half* srcs[3] = {g_xh, g_T1h, g_P2h};

#pragma unroll
    for (int part = 0; part < 3; part++) {
        const uint2* hp = (const uint2*)(srcs[part] + (long long)nb * CC);
        const float* wsp = ws + part * 4096;
        for (int c4 = 0; c4 < 16; c4++) {
            float av[4][4];
#pragma unroll
            for (int k = 0; k < 4; k++) {
                uint2 h = __ldg(&hp[k * 16 + c4]);
                float2 f0 = __half22float2(*(const half2*)&h.x);
                float2 f1 = __half22float2(*(const half2*)&h.y);
                av[k][0] = f0.x; av[k][1] = f0.y; av[k][2] = f1.x; av[k][3] = f1.y;
            }
#pragma unroll
            for (int t = 0; t < 4; t++) {
                unsigned long long pa[4];
#pragma unroll
                for (int k = 0; k < 4; k++) PACK2(pa[k], av[k][t], av[k][t]);
                const ulonglong2* wp =
                    (const ulonglong2*)(wsp + (c4 * 4 + t) * 64 + og * 16);
#pragma unroll
                for (int q = 0; q < 4; q++) {
                    ulonglong2 wv = wp[q];
#pragma unroll
                    for (int k = 0; k < 4; k++) {
                        FMA2(acc[k][q * 2 + 0], pa[k], wv.x);
                        FMA2(acc[k][q * 2 + 1], pa[k], wv.y);
                    }
                }
            }
        }
    }

    int jbase = og * 16;
    float bb[16];
#pragma unroll
    for (int o = 0; o < 16; o++) bb[o] = __ldg(&b[jbase + o]);

#pragma unroll
    for (int k = 0; k < 4; k++) {
        float4* outp = (float4*)(out + (long long)(nb + k) * CC + jbase);
#pragma unroll
        for (int q = 0; q < 4; q++) {
            float lo0, hi0, lo1, hi1;
            UNPACK2(lo0, hi0, acc[k][q * 2 + 0]);
            UNPACK2(lo1, hi1, acc[k][q * 2 + 1]);
            float4 r;
            r.x = fmaxf(lo0 + bb[q * 4 + 0], 0.0f);
            r.y = fmaxf(hi0 + bb[q * 4 + 1], 0.0f);
            r.z = fmaxf(lo1 + bb[q * 4 + 2], 0.0f);
            r.w = fmaxf(hi1 + bb[q * 4 + 3], 0.0f);
            outp[q] = r;
        }
    }
}

// ---------------------------------------------------------------------------
// Launch (6 kernels; prop1 is 4th -> gets profiled)
// ---------------------------------------------------------------------------
extern "C" void kernel_launch(void* const* d_in, const int* in_sizes, int n_in,
                              void* d_out, int out_size) {
    const float* x  = (const float*)d_in[0];   // [N, 64]
    const int*   ei = (const int*)d_in[1];     // [2, E]
    const float* ew = (const float*)d_in[2];   // [E]
    const float* W  = (const float*)d_in[3];   // [3, 64, 64]
    const float* b  = (const float*)d_in[4];   // [64]
    float* out = (float*)d_out;                // [N, 64]

    const int E = in_sizes[2];                 // 800000
    const int* row = ei;
    const int* col = ei + E;

    const int egrid = (NE + 255) / 256;

    deg_kernel<<<egrid, 256>>>(row, ew);
    scan_kernel<<<NBLK, 256>>>();
    scatter_convert_kernel<<<egrid, 256>>>(row, col, ew, (const float4*)x);

    const int pgrid = (NN * 8 + 255) / 256;
    prop1_kernel<<<pgrid, 256>>>();
    prop2_kernel<<<pgrid, 256>>>();

    epi_kernel<<<(NN + 255) / 256, 256>>>(W, b, out);
    (void)E; (void)n_in; (void)out_size;
}